// round 15
// baseline (speedup 1.0000x reference)
#include <cuda_runtime.h>
#include <cuda_fp16.h>
#include <cstdint>

// ---------------------------------------------------------------------------
// MultiHeadAttention (B=4, S=2048, D=1024, H=16, DK=64).
// Round 15: R14 + attention occupancy fix — 64-row q-tiles, warp tile 16x32
// (sacc/cacc 32->16 regs each), __launch_bounds__(256,3) -> 3 CTAs/SM.
// Output layout: d_out = [ x (8,388,608 f32) | attn (268,435,456 f32) ]
// ---------------------------------------------------------------------------

namespace {
constexpr int B  = 4;
constexpr int S  = 2048;
constexpr int D  = 1024;
constexpr int H  = 16;
constexpr int DK = 64;
constexpr size_t QH_ELEMS   = (size_t)B * H * S * DK;        // 8,388,608
constexpr size_t X_ELEMS    = (size_t)B * S * D;             // 8,388,608
constexpr size_t ATTN_ELEMS = (size_t)B * H * S * (size_t)S; // 268,435,456

// fp16 dense-GEMM tiling (R13/R14-proven): CTA 128x128, warp 64x32,
// K-chunk 32 halfs, two cp.async stages, ldmatrix fragments.
constexpr int KC  = 32;
constexpr int NCH = D / KC;                 // 32 chunks
constexpr int GST = 20;                     // words/row
constexpr int GTILE = 128 * GST;            // words per tile
constexpr int GEMM_SMEM = 4 * GTILE * 4;    // 40,960 B

// attention smem (32-bit words): 64-row tiles everywhere.
constexpr int AST = 36;
constexpr int AQ_OFF = 0;                   // Qs[64][36w] fp16, pre-scaled
constexpr int AK_OFF = AQ_OFF + 64 * AST;   // Ks[64][36w]
constexpr int AV_OFF = AK_OFF + 64 * AST;   // Vt[64][36w] (d rows, key cols)
constexpr int AP_OFF = AV_OFF + 64 * AST;   // Ps[64][36w]
constexpr int ARS_OFF = AP_OFF + 64 * AST;  // rs[2][64] floats
constexpr int AIV_OFF = ARS_OFF + 128;      // sinv[64] floats
constexpr int ATTN_SMEM = (AIV_OFF + 64) * 4;    // 37,632 B -> 3 CTAs/SM
}

// Scratch (allocation-free rule: __device__ globals)
__device__ __half g_qcv[X_ELEMS];          // fp16 copies of inputs
__device__ __half g_kcv[X_ELEMS];
__device__ __half g_vcv[X_ELEMS];
__device__ __half g_qh[QH_ELEMS];          // fp16, pre-scaled by 0.125
__device__ __half g_kh[QH_ELEMS];          // fp16
__device__ __half g_vt[QH_ELEMS];          // fp16; V transposed [bh][d][s]
__device__ __half g_ctx[X_ELEMS];          // fp16 (consumed by fc MMA)
__device__ __half g_eh[ATTN_ELEMS];        // fp16 unnormalized exp(S) scratch
__device__ float  g_x[X_ELEMS];            // fp32
__device__ float  g_rinv[(size_t)B * H * S];
__device__ __half g_wqt[(size_t)D * D];    // Wq^T  [N][K] fp16
__device__ __half g_wfct[(size_t)D * D];   // Wfc^T [N][K] fp16

// ---------------------------------------------------------------------------
// helpers
// ---------------------------------------------------------------------------
__device__ __forceinline__ uint32_t smem_to_u32(const void* p) {
    uint32_t a;
    asm("{ .reg .u64 t; cvta.to.shared.u64 t, %1; cvt.u32.u64 %0, t; }"
        : "=r"(a) : "l"(p));
    return a;
}
__device__ __forceinline__ uint32_t h2u(__half2 h) {
    uint32_t u;
    __builtin_memcpy(&u, &h, 4);
    return u;
}
__device__ __forceinline__ void mma_f16(float* d, const uint32_t* a, const uint32_t* b) {
    asm volatile(
        "mma.sync.aligned.m16n8k16.row.col.f32.f16.f16.f32 "
        "{%0,%1,%2,%3}, {%4,%5,%6,%7}, {%8,%9}, {%0,%1,%2,%3};"
        : "+f"(d[0]), "+f"(d[1]), "+f"(d[2]), "+f"(d[3])
        : "r"(a[0]), "r"(a[1]), "r"(a[2]), "r"(a[3]), "r"(b[0]), "r"(b[1]));
}
__device__ __forceinline__ void ldsm_x4(uint32_t* r, uint32_t addr) {
    asm volatile("ldmatrix.sync.aligned.m8n8.x4.shared.b16 {%0,%1,%2,%3}, [%4];"
        : "=r"(r[0]), "=r"(r[1]), "=r"(r[2]), "=r"(r[3]) : "r"(addr));
}
__device__ __forceinline__ void ldsm_x2(uint32_t* r, uint32_t addr) {
    asm volatile("ldmatrix.sync.aligned.m8n8.x2.shared.b16 {%0,%1}, [%2];"
        : "=r"(r[0]), "=r"(r[1]) : "r"(addr));
}
__device__ __forceinline__ void cp16(uint32_t dst, const void* src) {
    asm volatile("cp.async.cg.shared.global [%0], [%1], 16;" :: "r"(dst), "l"(src));
}
__device__ __forceinline__ void cp_commit() {
    asm volatile("cp.async.commit_group;" ::: "memory");
}
__device__ __forceinline__ void cp_wait0() {
    asm volatile("cp.async.wait_group 0;" ::: "memory");
}
__device__ __forceinline__ void cp_wait1() {
    asm volatile("cp.async.wait_group 1;" ::: "memory");
}
// exp via FMA pipe: magic-number range reduction + deg-5 poly (rel err ~2e-6).
__device__ __forceinline__ float fast_exp(float x) {
    const float L2E = 1.4426950408889634f;
    float t = fmaf(x, L2E, 12582912.0f);
    float n = t - 12582912.0f;
    float f = fmaf(x, L2E, -n);
    float p = 0.0013333558f;
    p = fmaf(p, f, 0.0096181291f);
    p = fmaf(p, f, 0.0555041087f);
    p = fmaf(p, f, 0.2402265069f);
    p = fmaf(p, f, 0.6931471806f);
    p = fmaf(p, f, 1.0f);
    return __int_as_float(__float_as_int(p) + (__float_as_int(t) << 23));
}

// ---------------------------------------------------------------------------
// K0a: convert q,k,v (fp32) -> fp16 gmem. blockIdx.y selects tensor.
// ---------------------------------------------------------------------------
__global__ __launch_bounds__(256) void convert_kernel(
    const float* __restrict__ q, const float* __restrict__ k,
    const float* __restrict__ v)
{
    const float* src = (blockIdx.y == 0) ? q : (blockIdx.y == 1) ? k : v;
    __half* dst = (blockIdx.y == 0) ? g_qcv : (blockIdx.y == 1) ? g_kcv : g_vcv;
    size_t i4 = (size_t)blockIdx.x * blockDim.x + threadIdx.x;   // float4 idx
    float4 fv = *((const float4*)src + i4);
    __half2 h0 = __floats2half2_rn(fv.x, fv.y);
    __half2 h1 = __floats2half2_rn(fv.z, fv.w);
    uint2 o = make_uint2(h2u(h0), h2u(h1));
    *((uint2*)dst + i4) = o;
}

// ---------------------------------------------------------------------------
// K0b: transpose Wq and Wfc once -> g_wqt / g_wfct (fp16 at store)
// ---------------------------------------------------------------------------
__global__ __launch_bounds__(256) void transpose_kernel(
    const float* __restrict__ Wq, const float* __restrict__ Wfc)
{
    __shared__ float tile[32][33];
    const float* src = blockIdx.z ? Wfc : Wq;
    __half*      dst = blockIdx.z ? g_wfct : g_wqt;
    int x = blockIdx.x * 32 + threadIdx.x;
    int y = blockIdx.y * 32 + threadIdx.y;
#pragma unroll
    for (int i = 0; i < 32; i += 8)
        tile[threadIdx.y + i][threadIdx.x] = src[(size_t)(y + i) * D + x];
    __syncthreads();
    int tx = blockIdx.y * 32 + threadIdx.x;
    int ty = blockIdx.x * 32 + threadIdx.y;
#pragma unroll
    for (int i = 0; i < 32; i += 8)
        dst[(size_t)(ty + i) * D + tx] =
            __float2half_rn(tile[threadIdx.x][threadIdx.y + i]);
}

// ---------------------------------------------------------------------------
// K1/K4: fp16 mma.sync GEMM, 2-stage cp.async pipeline, ldmatrix frags.
// (unchanged from R14)
// ---------------------------------------------------------------------------
__global__ __launch_bounds__(256) void gemm_f16_kernel(
    const __half* __restrict__ A0, const __half* __restrict__ A1,
    const __half* __restrict__ A2, const __half* __restrict__ Bt,
    const float* __restrict__ bias, const float* __restrict__ resid,
    float* __restrict__ O1f, int mode)
{
    extern __shared__ uint32_t smu[];
    const uint32_t smem_u = smem_to_u32(smu);

    const int tid  = threadIdx.x;
    const int wid  = tid >> 5, lane = tid & 31;
    const int g    = lane >> 2, tq = lane & 3;
    const int wm   = (wid >> 2) * 64;
    const int wn   = (wid & 3) * 32;
    const int n0   = blockIdx.x * 128;
    const int m0   = blockIdx.y * 128;

    const int mat  = lane >> 3;
    const int lrow = lane & 7;
    const int matb = (lane >> 3) & 1;
    const uint32_t aoff =
        ((uint32_t)((wm + (mat & 1) * 8 + lrow) * GST + (mat >> 1) * 4)) * 4;
    const uint32_t boff =
        ((uint32_t)((wn + lrow) * GST + matb * 4)) * 4;

    const __half* Ap;
    if (blockIdx.z == 0)      Ap = A0;
    else if (blockIdx.z == 1) Ap = A1;
    else                      Ap = A2;

    float acc[4][4][4];
#pragma unroll
    for (int i = 0; i < 4; i++)
#pragma unroll
        for (int j = 0; j < 4; j++)
#pragma unroll
            for (int r = 0; r < 4; r++) acc[i][j][r] = 0.f;

#pragma unroll
    for (int c0 = 0; c0 < 2; c0++) {
        const int kt = c0 * KC;
        const uint32_t sbase = smem_u + (uint32_t)(c0 * 2 * GTILE) * 4;
#pragma unroll
        for (int j = 0; j < 2; j++) {
            int idx = tid + j * 256;
            int row = idx >> 2, ch = idx & 3;
            uint32_t off = (uint32_t)(row * GST + ch * 4) * 4;
            cp16(sbase + off,             Ap + (size_t)(m0 + row) * D + kt + ch * 8);
            cp16(sbase + off + GTILE * 4, Bt + (size_t)(n0 + row) * D + kt + ch * 8);
        }
        cp_commit();
    }

    for (int c = 0; c < NCH; c++) {
        const int st = c & 1;
        if (c + 1 < NCH) cp_wait1(); else cp_wait0();
        __syncthreads();

        const uint32_t abase = smem_u + (uint32_t)(st * 2 * GTILE) * 4 + aoff;
        const uint32_t bbase = smem_u + (uint32_t)(st * 2 * GTILE + GTILE) * 4 + boff;

#pragma unroll
        for (int ks = 0; ks < 2; ks++) {
            const int kk = ks * 8;
            uint32_t a[4][4], b[4][2];
#pragma unroll
            for (int mf = 0; mf < 4; mf++)
                ldsm_x4(a[mf], abase + (uint32_t)(mf * 16 * GST + kk) * 4);
#pragma unroll
            for (int nf = 0; nf < 4; nf++)
                ldsm_x2(b[nf], bbase + (uint32_t)(nf * 8 * GST + kk) * 4);
#pragma unroll
            for (int mf = 0; mf < 4; mf++)
#pragma unroll
                for (int nf = 0; nf < 4; nf++)
                    mma_f16(acc[mf][nf], a[mf], b[nf]);
        }
        __syncthreads();

        if (c + 2 < NCH) {
            const int kt = (c + 2) * KC;
            const uint32_t sbase = smem_u + (uint32_t)(st * 2 * GTILE) * 4;
#pragma unroll
            for (int j = 0; j < 2; j++) {
                int idx = tid + j * 256;
                int row = idx >> 2, ch = idx & 3;
                uint32_t off = (uint32_t)(row * GST + ch * 4) * 4;
                cp16(sbase + off,             Ap + (size_t)(m0 + row) * D + kt + ch * 8);
                cp16(sbase + off + GTILE * 4, Bt + (size_t)(n0 + row) * D + kt + ch * 8);
            }
            cp_commit();
        }
    }

    const float osc = (blockIdx.z == 0 && mode == 0) ? 0.125f : 1.0f;

#pragma unroll
    for (int mf = 0; mf < 4; mf++) {
#pragma unroll
        for (int nf = 0; nf < 4; nf++) {
            const int m = m0 + wm + mf * 16 + g;
            const int n = n0 + wn + nf * 8 + tq * 2;
            float bx = bias[n], by = bias[n + 1];
#pragma unroll
            for (int half = 0; half < 2; half++) {
                const int mm = m + half * 8;
                float vx = acc[mf][nf][half * 2 + 0] + bx;
                float vy = acc[mf][nf][half * 2 + 1] + by;
                if (mode == 0) {
                    vx *= osc; vy *= osc;
                    const int h = n >> 6, dk = n & 63;
                    const int bb_ = mm >> 11, s = mm & 2047;
                    if (blockIdx.z == 2) {
                        __half* vtb = &g_vt[(((size_t)bb_ * H + h) * DK + dk) * S + s];
                        vtb[0] = __float2half_rn(vx);
                        vtb[S] = __float2half_rn(vy);
                    } else {
                        __half* orow = (blockIdx.z == 0 ? g_qh : g_kh)
                                       + (((size_t)bb_ * H + h) * S + s) * DK;
                        *(__half2*)&orow[dk] = __floats2half2_rn(vx, vy);
                    }
                } else {
                    const float* rr = resid + (size_t)mm * D + n;
                    float2 r2 = *(const float2*)rr;
                    float2* p = (float2*)&O1f[(size_t)mm * D + n];
                    *p = make_float2(vx + r2.x, vy + r2.y);
                }
            }
        }
    }
}

// ---------------------------------------------------------------------------
// K2: attention, 64-row q-tiles. grid (32 q-tiles, 64 bh), block 256,
// warp grid 4q x 2k, warp tile 16x32 (sacc/cacc = 16 regs each).
// fp16 mma + ldmatrix; coalesced E-writeback from Ps; 3 CTAs/SM.
// ---------------------------------------------------------------------------
__global__ __launch_bounds__(256, 3) void attn_mma_kernel()
{
    extern __shared__ uint32_t smu[];
    uint32_t* Ps = smu + AP_OFF;
    float* rs    = (float*)(smu + ARS_OFF);
    float* sinv  = (float*)(smu + AIV_OFF);
    const uint32_t smem_u = smem_to_u32(smu);
    const uint32_t qs_u = smem_u + AQ_OFF * 4;
    const uint32_t ks_u = smem_u + AK_OFF * 4;
    const uint32_t vt_u = smem_u + AV_OFF * 4;
    const uint32_t ps_u = smem_u + AP_OFF * 4;

    const int bh = blockIdx.y;
    const int q0 = blockIdx.x * 64;
    const int tid = threadIdx.x;
    const int wid = tid >> 5, lane = tid & 31;
    const int g = lane >> 2, tq = lane & 3;
    const int wm = (wid >> 1) * 16;      // q rows of this warp
    const int wn = (wid & 1) * 32;       // k cols (S) / d cols (ctx)

    // ldmatrix per-lane address components (stride AST)
    const int mat  = lane >> 3;
    const int lrow = lane & 7;
    const int matb = (lane >> 3) & 1;
    const uint32_t aoff =
        ((uint32_t)((wm + (mat & 1) * 8 + lrow) * AST + (mat >> 1) * 4)) * 4;
    const uint32_t boff =
        ((uint32_t)((wn + lrow) * AST + matb * 4)) * 4;

    // prologue: Q + K(0) in one group, V(0) in a second group
    // Q: 64 rows x 8 chunks = 512, 2/thread; K/V same
#pragma unroll
    for (int i = 0; i < 2; i++) {
        int idx = tid + i * 256;
        int row = idx >> 3, ch = idx & 7;
        cp16(qs_u + (uint32_t)(row * AST + ch * 4) * 4,
             &g_qh[((size_t)bh * S + q0 + row) * DK + ch * 8]);
    }
#pragma unroll
    for (int i = 0; i < 2; i++) {
        int idx = tid + i * 256;
        int row = idx >> 3, ch = idx & 7;
        cp16(ks_u + (uint32_t)(row * AST + ch * 4) * 4,
             &g_kh[((size_t)bh * S + row) * DK + ch * 8]);
    }
    cp_commit();
#pragma unroll
    for (int i = 0; i < 2; i++) {
        int idx = tid + i * 256;
        int row = idx >> 3, ch = idx & 7;
        cp16(vt_u + (uint32_t)(row * AST + ch * 4) * 4,
             &g_vt[((size_t)bh * DK + row) * S + ch * 8]);
    }
    cp_commit();

    float cacc[4][4];
    float rsum[2] = {0.f, 0.f};
#pragma unroll
    for (int nf = 0; nf < 4; nf++)
#pragma unroll
        for (int r = 0; r < 4; r++) cacc[nf][r] = 0.f;

    for (int kt = 0; kt < S / 64; kt++) {
        const int k0 = kt * 64;

        cp_wait1();            // Q + K(kt) arrived (V may be in flight)
        __syncthreads();

        // S = Q·K^T  (k = d = 64 -> 4 fp16 k16 steps); ldmatrix frags
        float sacc[4][4];
#pragma unroll
        for (int nf = 0; nf < 4; nf++)
#pragma unroll
            for (int r = 0; r < 4; r++) sacc[nf][r] = 0.f;
#pragma unroll
        for (int ks = 0; ks < 4; ks++) {
            const int kk = ks * 8;
            uint32_t a[4], b[4][2];
            ldsm_x4(a, qs_u + aoff + (uint32_t)kk * 4);
#pragma unroll
            for (int nf = 0; nf < 4; nf++)
                ldsm_x2(b[nf], ks_u + boff + (uint32_t)(nf * 8 * AST + kk) * 4);
#pragma unroll
            for (int nf = 0; nf < 4; nf++)
                mma_f16(sacc[nf], a, b[nf]);
        }

        // exp, rowsum, P -> smem (fp16)
        const int r0 = wm + g;
#pragma unroll
        for (int nf = 0; nf < 4; nf++) {
            const int c0 = wn + nf * 8 + tq * 2;
            float e00 = fast_exp(sacc[nf][0]);
            float e01 = fast_exp(sacc[nf][1]);
            float e10 = fast_exp(sacc[nf][2]);
            float e11 = fast_exp(sacc[nf][3]);
            rsum[0] += e00 + e01;
            rsum[1] += e10 + e11;
            Ps[r0 * AST + (c0 >> 1)]       = h2u(__floats2half2_rn(e00, e01));
            Ps[(r0 + 8) * AST + (c0 >> 1)] = h2u(__floats2half2_rn(e10, e11));
        }

        cp_wait0();            // V(kt) arrived
        __syncthreads();       // publish V + Ps; Ks fully consumed

        // issue K(kt+1) — overlaps the P·V phase below
        if (kt + 1 < S / 64) {
            const int nk0 = k0 + 64;
#pragma unroll
            for (int i = 0; i < 2; i++) {
                int idx = tid + i * 256;
                int row = idx >> 3, ch = idx & 7;
                cp16(ks_u + (uint32_t)(row * AST + ch * 4) * 4,
                     &g_kh[((size_t)bh * S + nk0 + row) * DK + ch * 8]);
            }
            cp_commit();
        }

        // ctx += P·V (k = keys = 64 -> 4 fp16 k16 steps); ldmatrix frags
#pragma unroll
        for (int ks = 0; ks < 4; ks++) {
            const int kk = ks * 8;
            uint32_t a[4], b[4][2];
            ldsm_x4(a, ps_u + aoff + (uint32_t)kk * 4);
#pragma unroll
            for (int nf = 0; nf < 4; nf++)
                ldsm_x2(b[nf], vt_u + boff + (uint32_t)(nf * 8 * AST + kk) * 4);
#pragma unroll
            for (int nf = 0; nf < 4; nf++)
                mma_f16(cacc[nf], a, b[nf]);
        }

        // coalesced E writeback: Ps -> g_eh tile block (64 rows x 64 halfs)
        {
            __half* ebase = &g_eh[((size_t)bh * S + q0) * S + k0];
#pragma unroll
            for (int i = 0; i < 2; i++) {
                int idx = tid + i * 256;
                int row = idx >> 3, c4 = idx & 7;
                uint4 val = *(const uint4*)&Ps[row * AST + c4 * 4];
                *(uint4*)(ebase + (size_t)row * S + c4 * 8) = val;
            }
        }
        __syncthreads();       // Vt + Ps fully consumed

        // issue V(kt+1) — overlaps the next tile's QK phase
        if (kt + 1 < S / 64) {
            const int nk0 = k0 + 64;
#pragma unroll
            for (int i = 0; i < 2; i++) {
                int idx = tid + i * 256;
                int row = idx >> 3, ch = idx & 7;
                cp16(vt_u + (uint32_t)(row * AST + ch * 4) * 4,
                     &g_vt[((size_t)bh * DK + row) * S + nk0 + ch * 8]);
            }
            cp_commit();
        }
    }

    // rowsum: reduce across tq lanes, publish per warp k-half, combine
#pragma unroll
    for (int hh = 0; hh < 2; hh++) {
        float v = rsum[hh];
        v += __shfl_xor_sync(0xffffffffu, v, 1);
        v += __shfl_xor_sync(0xffffffffu, v, 2);
        rsum[hh] = v;
    }
    if (tq == 0) {
#pragma unroll
        for (int hh = 0; hh < 2; hh++)
            rs[(wid & 1) * 64 + wm + hh * 8 + g] = rsum[hh];
    }
    __syncthreads();
    if (tid < 64) {
        float iv = 1.0f / (rs[tid] + rs[64 + tid]);
        g_rinv[(size_t)bh * S + q0 + tid] = iv;
        sinv[tid] = iv;
    }
    __syncthreads();

    // scaled ctx -> g_ctx (fp16: consumed only by fc's fp16 MMA)
    const int b_ = bh >> 4, h_ = bh & 15;
    {
        const int r0 = wm + g;
        const float iv0 = sinv[r0], iv1 = sinv[r0 + 8];
#pragma unroll
        for (int nf = 0; nf < 4; nf++) {
            const int c0 = wn + nf * 8 + tq * 2;
            *(__half2*)&g_ctx[((size_t)b_ * S + q0 + r0) * D + h_ * DK + c0] =
                __floats2half2_rn(cacc[nf][0] * iv0, cacc[nf][1] * iv0);
            *(__half2*)&g_ctx[((size_t)b_ * S + q0 + r0 + 8) * D + h_ * DK + c0] =
                __floats2half2_rn(cacc[nf][2] * iv1, cacc[nf][3] * iv1);
        }
    }
}

// ---------------------------------------------------------------------------
// K3: normalize: attn_out[row][*] = half2float(g_eh[row][*]) * rinv[row]
// ---------------------------------------------------------------------------
__global__ __launch_bounds__(256) void attn_scale_kernel(float* __restrict__ attn)
{
    size_t idx4 = (size_t)blockIdx.x * blockDim.x + threadIdx.x;  // 4-elem idx
    size_t row  = idx4 >> 9;                                      // 512 groups/row
    float inv = g_rinv[row];
    uint2 e = __ldcs((const uint2*)g_eh + idx4);
    __half2 h0, h1;
    __builtin_memcpy(&h0, &e.x, 4);
    __builtin_memcpy(&h1, &e.y, 4);
    float2 f0 = __half22float2(h0);
    float2 f1 = __half22float2(h1);
    float4 v = make_float4(f0.x * inv, f0.y * inv, f1.x * inv, f1.y * inv);
    __stcs((float4*)attn + idx4, v);
}

// ---------------------------------------------------------------------------
// K5: LayerNorm over last dim (1024). One block (256 thr) per row.
// ---------------------------------------------------------------------------
__global__ __launch_bounds__(256) void ln_kernel(
    const float* __restrict__ gamma, const float* __restrict__ beta,
    float* __restrict__ out)
{
    __shared__ float s1[8], s2[8];
    __shared__ float sm_mean, sm_rstd;
    const int row = blockIdx.x;
    const int t   = threadIdx.x;
    const float* x = g_x + (size_t)row * D;

    float4 v = *(const float4*)(x + t * 4);
    float sum = v.x + v.y + v.z + v.w;
    float sq  = v.x * v.x + v.y * v.y + v.z * v.z + v.w * v.w;
#pragma unroll
    for (int m = 16; m >= 1; m >>= 1) {
        sum += __shfl_xor_sync(0xffffffffu, sum, m);
        sq  += __shfl_xor_sync(0xffffffffu, sq, m);
    }
    const int warp = t >> 5, lane = t & 31;
    if (lane == 0) { s1[warp] = sum; s2[warp] = sq; }
    __syncthreads();
    if (t == 0) {
        float a = 0.f, c = 0.f;
#pragma unroll
        for (int w = 0; w < 8; w++) { a += s1[w]; c += s2[w]; }
        float mean = a * (1.0f / D);
        float var  = c * (1.0f / D) - mean * mean;
        sm_mean = mean;
        sm_rstd = rsqrtf(var + 1e-6f);
    }
    __syncthreads();
    const float mean = sm_mean, r = sm_rstd;
    float4 g4 = *(const float4*)(gamma + t * 4);
    float4 b4 = *(const float4*)(beta + t * 4);
    float4 o;
    o.x = (v.x - mean) * r * g4.x + b4.x;
    o.y = (v.y - mean) * r * g4.y + b4.y;
    o.z = (v.z - mean) * r * g4.z + b4.z;
    o.w = (v.w - mean) * r * g4.w + b4.w;
    *(float4*)(out + (size_t)row * D + t * 4) = o;
}

// ---------------------------------------------------------------------------
extern "C" void kernel_launch(void* const* d_in, const int* in_sizes, int n_in,
                              void* d_out, int out_size)
{
    const float* q     = (const float*)d_in[0];
    const float* k     = (const float*)d_in[1];
    const float* v     = (const float*)d_in[2];
    const float* Wq    = (const float*)d_in[3];
    const float* bq    = (const float*)d_in[4];
    const float* Wfc   = (const float*)d_in[5];
    const float* bfc   = (const float*)d_in[6];
    const float* gamma = (const float*)d_in[7];
    const float* beta  = (const float*)d_in[8];

    float* out_x    = (float*)d_out;
    float* out_attn = out_x + X_ELEMS;

    cudaFuncSetAttribute(gemm_f16_kernel,
                         cudaFuncAttributeMaxDynamicSharedMemorySize, GEMM_SMEM);
    cudaFuncSetAttribute(attn_mma_kernel,
                         cudaFuncAttributeMaxDynamicSharedMemorySize, ATTN_SMEM);

    __half *qcv_p, *kcv_p, *vcv_p, *wqt_p, *wfct_p, *ctx_p;
    float *x_p;
    cudaGetSymbolAddress((void**)&qcv_p,  g_qcv);
    cudaGetSymbolAddress((void**)&kcv_p,  g_kcv);
    cudaGetSymbolAddress((void**)&vcv_p,  g_vcv);
    cudaGetSymbolAddress((void**)&wqt_p,  g_wqt);
    cudaGetSymbolAddress((void**)&wfct_p, g_wfct);
    cudaGetSymbolAddress((void**)&ctx_p,  g_ctx);
    cudaGetSymbolAddress((void**)&x_p,    g_x);

    convert_kernel<<<dim3((unsigned)(X_ELEMS / 4 / 256), 3), 256>>>(q, k, v);
    transpose_kernel<<<dim3(32, 32, 2), dim3(32, 8)>>>(Wq, Wfc);
    gemm_f16_kernel<<<dim3(8, 64, 3), 256, GEMM_SMEM>>>(
        qcv_p, kcv_p, vcv_p, wqt_p, bq, nullptr, nullptr, 0);
    attn_mma_kernel<<<dim3(32, 64), 256, ATTN_SMEM>>>();
    attn_scale_kernel<<<(unsigned)(ATTN_ELEMS / 4 / 256), 256>>>(out_attn);
    gemm_f16_kernel<<<dim3(8, 64, 1), 256, GEMM_SMEM>>>(
        ctx_p, ctx_p, ctx_p, wfct_p, bfc, q, x_p, 1);
    ln_kernel<<<B * S, 256>>>(gamma, beta, out_x);
}

// round 16
// speedup vs baseline: 1.0659x; 1.0659x over previous
#include <cuda_runtime.h>
#include <cuda_fp16.h>
#include <cstdint>

// ---------------------------------------------------------------------------
// MultiHeadAttention (B=4, S=2048, D=1024, H=16, DK=64).
// Round 16: R14 (best: 873us) + stmatrix.x4 for Ps stores and pairwise
// ldmatrix.x4 for B fragments (attention + dense GEMM). Bit-identical data.
// Output layout: d_out = [ x (8,388,608 f32) | attn (268,435,456 f32) ]
// ---------------------------------------------------------------------------

namespace {
constexpr int B  = 4;
constexpr int S  = 2048;
constexpr int D  = 1024;
constexpr int H  = 16;
constexpr int DK = 64;
constexpr size_t QH_ELEMS   = (size_t)B * H * S * DK;        // 8,388,608
constexpr size_t X_ELEMS    = (size_t)B * S * D;             // 8,388,608
constexpr size_t ATTN_ELEMS = (size_t)B * H * S * (size_t)S; // 268,435,456

// fp16 dense-GEMM tiling: CTA 128x128, warp 64x32 (2x4 warps),
// K-chunk 32 halfs (2 k16 steps), two cp.async stages.
constexpr int KC  = 32;
constexpr int NCH = D / KC;                 // 32 chunks
constexpr int GST = 20;                     // words/row
constexpr int GTILE = 128 * GST;            // words per tile
constexpr int GEMM_SMEM = 4 * GTILE * 4;    // 40,960 B

// attention smem (32-bit words), R14-proven (128-row q-tiles).
constexpr int AST = 36;
constexpr int AQ_OFF = 0;                   // Qs[128][36w] fp16, pre-scaled
constexpr int AK_OFF = AQ_OFF + 128 * AST;  // Ks[64][36w]
constexpr int AV_OFF = AK_OFF + 64 * AST;   // Vt[64][36w] (d rows, key cols)
constexpr int AP_OFF = AV_OFF + 64 * AST;   // Ps[128][36w]
constexpr int ARS_OFF = AP_OFF + 128 * AST; // rs[2][128] floats
constexpr int AIV_OFF = ARS_OFF + 256;      // sinv[128] floats
constexpr int ATTN_SMEM = (AIV_OFF + 128) * 4;   // 56,832 B
}

// Scratch (allocation-free rule: __device__ globals)
__device__ __half g_qcv[X_ELEMS];          // fp16 copies of inputs
__device__ __half g_kcv[X_ELEMS];
__device__ __half g_vcv[X_ELEMS];
__device__ __half g_qh[QH_ELEMS];          // fp16, pre-scaled by 0.125
__device__ __half g_kh[QH_ELEMS];          // fp16
__device__ __half g_vt[QH_ELEMS];          // fp16; V transposed [bh][d][s]
__device__ __half g_ctx[X_ELEMS];          // fp16 (consumed by fc MMA)
__device__ __half g_eh[ATTN_ELEMS];        // fp16 unnormalized exp(S) scratch
__device__ float  g_x[X_ELEMS];            // fp32
__device__ float  g_rinv[(size_t)B * H * S];
__device__ __half g_wqt[(size_t)D * D];    // Wq^T  [N][K] fp16
__device__ __half g_wfct[(size_t)D * D];   // Wfc^T [N][K] fp16

// ---------------------------------------------------------------------------
// helpers
// ---------------------------------------------------------------------------
__device__ __forceinline__ uint32_t smem_to_u32(const void* p) {
    uint32_t a;
    asm("{ .reg .u64 t; cvta.to.shared.u64 t, %1; cvt.u32.u64 %0, t; }"
        : "=r"(a) : "l"(p));
    return a;
}
__device__ __forceinline__ uint32_t h2u(__half2 h) {
    uint32_t u;
    __builtin_memcpy(&u, &h, 4);
    return u;
}
__device__ __forceinline__ void mma_f16(float* d, const uint32_t* a, const uint32_t* b) {
    asm volatile(
        "mma.sync.aligned.m16n8k16.row.col.f32.f16.f16.f32 "
        "{%0,%1,%2,%3}, {%4,%5,%6,%7}, {%8,%9}, {%0,%1,%2,%3};"
        : "+f"(d[0]), "+f"(d[1]), "+f"(d[2]), "+f"(d[3])
        : "r"(a[0]), "r"(a[1]), "r"(a[2]), "r"(a[3]), "r"(b[0]), "r"(b[1]));
}
__device__ __forceinline__ void ldsm_x4(uint32_t* r, uint32_t addr) {
    asm volatile("ldmatrix.sync.aligned.m8n8.x4.shared.b16 {%0,%1,%2,%3}, [%4];"
        : "=r"(r[0]), "=r"(r[1]), "=r"(r[2]), "=r"(r[3]) : "r"(addr));
}
__device__ __forceinline__ void stsm_x4(uint32_t addr, const uint32_t* r) {
    asm volatile("stmatrix.sync.aligned.m8n8.x4.shared.b16 [%0], {%1,%2,%3,%4};"
        :: "r"(addr), "r"(r[0]), "r"(r[1]), "r"(r[2]), "r"(r[3]) : "memory");
}
__device__ __forceinline__ void cp16(uint32_t dst, const void* src) {
    asm volatile("cp.async.cg.shared.global [%0], [%1], 16;" :: "r"(dst), "l"(src));
}
__device__ __forceinline__ void cp_commit() {
    asm volatile("cp.async.commit_group;" ::: "memory");
}
__device__ __forceinline__ void cp_wait0() {
    asm volatile("cp.async.wait_group 0;" ::: "memory");
}
__device__ __forceinline__ void cp_wait1() {
    asm volatile("cp.async.wait_group 1;" ::: "memory");
}
// exp via FMA pipe: magic-number range reduction + deg-5 poly (rel err ~2e-6).
__device__ __forceinline__ float fast_exp(float x) {
    const float L2E = 1.4426950408889634f;
    float t = fmaf(x, L2E, 12582912.0f);
    float n = t - 12582912.0f;
    float f = fmaf(x, L2E, -n);
    float p = 0.0013333558f;
    p = fmaf(p, f, 0.0096181291f);
    p = fmaf(p, f, 0.0555041087f);
    p = fmaf(p, f, 0.2402265069f);
    p = fmaf(p, f, 0.6931471806f);
    p = fmaf(p, f, 1.0f);
    return __int_as_float(__float_as_int(p) + (__float_as_int(t) << 23));
}

// ---------------------------------------------------------------------------
// K0a: convert q,k,v (fp32) -> fp16 gmem. blockIdx.y selects tensor.
// ---------------------------------------------------------------------------
__global__ __launch_bounds__(256) void convert_kernel(
    const float* __restrict__ q, const float* __restrict__ k,
    const float* __restrict__ v)
{
    const float* src = (blockIdx.y == 0) ? q : (blockIdx.y == 1) ? k : v;
    __half* dst = (blockIdx.y == 0) ? g_qcv : (blockIdx.y == 1) ? g_kcv : g_vcv;
    size_t i4 = (size_t)blockIdx.x * blockDim.x + threadIdx.x;   // float4 idx
    float4 fv = *((const float4*)src + i4);
    __half2 h0 = __floats2half2_rn(fv.x, fv.y);
    __half2 h1 = __floats2half2_rn(fv.z, fv.w);
    uint2 o = make_uint2(h2u(h0), h2u(h1));
    *((uint2*)dst + i4) = o;
}

// ---------------------------------------------------------------------------
// K0b: transpose Wq and Wfc once -> g_wqt / g_wfct (fp16 at store)
// ---------------------------------------------------------------------------
__global__ __launch_bounds__(256) void transpose_kernel(
    const float* __restrict__ Wq, const float* __restrict__ Wfc)
{
    __shared__ float tile[32][33];
    const float* src = blockIdx.z ? Wfc : Wq;
    __half*      dst = blockIdx.z ? g_wfct : g_wqt;
    int x = blockIdx.x * 32 + threadIdx.x;
    int y = blockIdx.y * 32 + threadIdx.y;
#pragma unroll
    for (int i = 0; i < 32; i += 8)
        tile[threadIdx.y + i][threadIdx.x] = src[(size_t)(y + i) * D + x];
    __syncthreads();
    int tx = blockIdx.y * 32 + threadIdx.x;
    int ty = blockIdx.x * 32 + threadIdx.y;
#pragma unroll
    for (int i = 0; i < 32; i += 8)
        dst[(size_t)(ty + i) * D + tx] =
            __float2half_rn(tile[threadIdx.x][threadIdx.y + i]);
}

// ---------------------------------------------------------------------------
// K1/K4: fp16 mma.sync GEMM, 2-stage cp.async pipeline, ldmatrix frags
// (A: x4; B: pairwise x4 covering two nf tiles at once).
// mode 0: proj -> fp16 outputs (z=0 qh scaled by 0.125, z=1 kh, z=2 Vt).
// mode 1: fc (A = g_ctx fp16, B = Wfc^T fp16) -> fp32 g_x + resid.
// ---------------------------------------------------------------------------
__global__ __launch_bounds__(256) void gemm_f16_kernel(
    const __half* __restrict__ A0, const __half* __restrict__ A1,
    const __half* __restrict__ A2, const __half* __restrict__ Bt,
    const float* __restrict__ bias, const float* __restrict__ resid,
    float* __restrict__ O1f, int mode)
{
    extern __shared__ uint32_t smu[];
    const uint32_t smem_u = smem_to_u32(smu);

    const int tid  = threadIdx.x;
    const int wid  = tid >> 5, lane = tid & 31;
    const int g    = lane >> 2, tq = lane & 3;
    const int wm   = (wid >> 2) * 64;
    const int wn   = (wid & 3) * 32;
    const int n0   = blockIdx.x * 128;
    const int m0   = blockIdx.y * 128;

    const int mat  = lane >> 3;           // 0..3
    const int lrow = lane & 7;
    // A x4: matrices (m-half, k-half)
    const uint32_t aoff =
        ((uint32_t)((wm + (mat & 1) * 8 + lrow) * GST + (mat >> 1) * 4)) * 4;
    // B pairwise x4: matrices (nf-sub, k-half): rows wn + (lane>>4)*8 + lrow
    const uint32_t boff4 =
        ((uint32_t)((wn + (lane >> 4) * 8 + lrow) * GST + ((lane >> 3) & 1) * 4)) * 4;

    const __half* Ap;
    if (blockIdx.z == 0)      Ap = A0;
    else if (blockIdx.z == 1) Ap = A1;
    else                      Ap = A2;

    float acc[4][4][4];
#pragma unroll
    for (int i = 0; i < 4; i++)
#pragma unroll
        for (int j = 0; j < 4; j++)
#pragma unroll
            for (int r = 0; r < 4; r++) acc[i][j][r] = 0.f;

#pragma unroll
    for (int c0 = 0; c0 < 2; c0++) {
        const int kt = c0 * KC;
        const uint32_t sbase = smem_u + (uint32_t)(c0 * 2 * GTILE) * 4;
#pragma unroll
        for (int j = 0; j < 2; j++) {
            int idx = tid + j * 256;
            int row = idx >> 2, ch = idx & 3;
            uint32_t off = (uint32_t)(row * GST + ch * 4) * 4;
            cp16(sbase + off,             Ap + (size_t)(m0 + row) * D + kt + ch * 8);
            cp16(sbase + off + GTILE * 4, Bt + (size_t)(n0 + row) * D + kt + ch * 8);
        }
        cp_commit();
    }

    for (int c = 0; c < NCH; c++) {
        const int st = c & 1;
        if (c + 1 < NCH) cp_wait1(); else cp_wait0();
        __syncthreads();

        const uint32_t abase = smem_u + (uint32_t)(st * 2 * GTILE) * 4 + aoff;
        const uint32_t bbase = smem_u + (uint32_t)(st * 2 * GTILE + GTILE) * 4 + boff4;

#pragma unroll
        for (int ks = 0; ks < 2; ks++) {
            const int kk = ks * 8;
            uint32_t a[4][4], b[4][2];
#pragma unroll
            for (int mf = 0; mf < 4; mf++)
                ldsm_x4(a[mf], abase + (uint32_t)(mf * 16 * GST + kk) * 4);
#pragma unroll
            for (int p = 0; p < 2; p++) {
                uint32_t t4[4];
                ldsm_x4(t4, bbase + (uint32_t)(p * 16 * GST + kk) * 4);
                b[2 * p + 0][0] = t4[0]; b[2 * p + 0][1] = t4[1];
                b[2 * p + 1][0] = t4[2]; b[2 * p + 1][1] = t4[3];
            }
#pragma unroll
            for (int mf = 0; mf < 4; mf++)
#pragma unroll
                for (int nf = 0; nf < 4; nf++)
                    mma_f16(acc[mf][nf], a[mf], b[nf]);
        }
        __syncthreads();

        if (c + 2 < NCH) {
            const int kt = (c + 2) * KC;
            const uint32_t sbase = smem_u + (uint32_t)(st * 2 * GTILE) * 4;
#pragma unroll
            for (int j = 0; j < 2; j++) {
                int idx = tid + j * 256;
                int row = idx >> 2, ch = idx & 3;
                uint32_t off = (uint32_t)(row * GST + ch * 4) * 4;
                cp16(sbase + off,             Ap + (size_t)(m0 + row) * D + kt + ch * 8);
                cp16(sbase + off + GTILE * 4, Bt + (size_t)(n0 + row) * D + kt + ch * 8);
            }
            cp_commit();
        }
    }

    const float osc = (blockIdx.z == 0 && mode == 0) ? 0.125f : 1.0f;

#pragma unroll
    for (int mf = 0; mf < 4; mf++) {
#pragma unroll
        for (int nf = 0; nf < 4; nf++) {
            const int m = m0 + wm + mf * 16 + g;
            const int n = n0 + wn + nf * 8 + tq * 2;
            float bx = bias[n], by = bias[n + 1];
#pragma unroll
            for (int half = 0; half < 2; half++) {
                const int mm = m + half * 8;
                float vx = acc[mf][nf][half * 2 + 0] + bx;
                float vy = acc[mf][nf][half * 2 + 1] + by;
                if (mode == 0) {
                    vx *= osc; vy *= osc;
                    const int h = n >> 6, dk = n & 63;
                    const int bb_ = mm >> 11, s = mm & 2047;
                    if (blockIdx.z == 2) {
                        __half* vtb = &g_vt[(((size_t)bb_ * H + h) * DK + dk) * S + s];
                        vtb[0] = __float2half_rn(vx);
                        vtb[S] = __float2half_rn(vy);
                    } else {
                        __half* orow = (blockIdx.z == 0 ? g_qh : g_kh)
                                       + (((size_t)bb_ * H + h) * S + s) * DK;
                        *(__half2*)&orow[dk] = __floats2half2_rn(vx, vy);
                    }
                } else {
                    const float* rr = resid + (size_t)mm * D + n;
                    float2 r2 = *(const float2*)rr;
                    float2* p = (float2*)&O1f[(size_t)mm * D + n];
                    *p = make_float2(vx + r2.x, vy + r2.y);
                }
            }
        }
    }
}

// ---------------------------------------------------------------------------
// K2: attention (R14 shape) + stmatrix Ps stores + pairwise-x4 B loads.
// grid (16 q-tiles, 64 bh), block 256. Warp grid 4x2, warp tile 32x32.
// ---------------------------------------------------------------------------
__global__ __launch_bounds__(256, 2) void attn_mma_kernel()
{
    extern __shared__ uint32_t smu[];
    uint32_t* Ps = smu + AP_OFF;
    float* rs    = (float*)(smu + ARS_OFF);
    float* sinv  = (float*)(smu + AIV_OFF);
    const uint32_t smem_u = smem_to_u32(smu);
    const uint32_t qs_u = smem_u + AQ_OFF * 4;
    const uint32_t ks_u = smem_u + AK_OFF * 4;
    const uint32_t vt_u = smem_u + AV_OFF * 4;
    const uint32_t ps_u = smem_u + AP_OFF * 4;

    const int bh = blockIdx.y;
    const int q0 = blockIdx.x * 128;
    const int tid = threadIdx.x;
    const int wid = tid >> 5, lane = tid & 31;
    const int g = lane >> 2, tq = lane & 3;
    const int wm = (wid >> 1) * 32;
    const int wn = (wid & 1) * 32;

    const int mat  = lane >> 3;
    const int lrow = lane & 7;
    const uint32_t aoff =
        ((uint32_t)((wm + (mat & 1) * 8 + lrow) * AST + (mat >> 1) * 4)) * 4;
    const uint32_t boff4 =
        ((uint32_t)((wn + (lane >> 4) * 8 + lrow) * AST + ((lane >> 3) & 1) * 4)) * 4;
    // stmatrix: matrix nf = lane>>3, row lrow, col words wn/2 + nf*4
    const uint32_t poff =
        ((uint32_t)((wm + lrow) * AST + (wn >> 1) + mat * 4)) * 4;

    // prologue: Q + K(0) in one group, V(0) in a second group
#pragma unroll
    for (int i = 0; i < 4; i++) {
        int idx = tid + i * 256;
        int row = idx >> 3, ch = idx & 7;
        cp16(qs_u + (uint32_t)(row * AST + ch * 4) * 4,
             &g_qh[((size_t)bh * S + q0 + row) * DK + ch * 8]);
    }
#pragma unroll
    for (int i = 0; i < 2; i++) {
        int idx = tid + i * 256;
        int row = idx >> 3, ch = idx & 7;
        cp16(ks_u + (uint32_t)(row * AST + ch * 4) * 4,
             &g_kh[((size_t)bh * S + row) * DK + ch * 8]);
    }
    cp_commit();
#pragma unroll
    for (int i = 0; i < 2; i++) {
        int idx = tid + i * 256;
        int row = idx >> 3, ch = idx & 7;
        cp16(vt_u + (uint32_t)(row * AST + ch * 4) * 4,
             &g_vt[((size_t)bh * DK + row) * S + ch * 8]);
    }
    cp_commit();

    float cacc[2][4][4];
    float rsum[2][2] = {{0.f, 0.f}, {0.f, 0.f}};
#pragma unroll
    for (int mf = 0; mf < 2; mf++)
#pragma unroll
        for (int nf = 0; nf < 4; nf++)
#pragma unroll
            for (int r = 0; r < 4; r++) cacc[mf][nf][r] = 0.f;

    for (int kt = 0; kt < S / 64; kt++) {
        const int k0 = kt * 64;

        cp_wait1();            // Q + K(kt) arrived (V may be in flight)
        __syncthreads();

        // S = Q·K^T  (4 fp16 k16 steps); ldmatrix frags
        float sacc[2][4][4];
#pragma unroll
        for (int mf = 0; mf < 2; mf++)
#pragma unroll
            for (int nf = 0; nf < 4; nf++)
#pragma unroll
                for (int r = 0; r < 4; r++) sacc[mf][nf][r] = 0.f;
#pragma unroll
        for (int ks = 0; ks < 4; ks++) {
            const int kk = ks * 8;
            uint32_t a[2][4], b[4][2];
#pragma unroll
            for (int mf = 0; mf < 2; mf++)
                ldsm_x4(a[mf], qs_u + aoff + (uint32_t)(mf * 16 * AST + kk) * 4);
#pragma unroll
            for (int p = 0; p < 2; p++) {
                uint32_t t4[4];
                ldsm_x4(t4, ks_u + boff4 + (uint32_t)(p * 16 * AST + kk) * 4);
                b[2 * p + 0][0] = t4[0]; b[2 * p + 0][1] = t4[1];
                b[2 * p + 1][0] = t4[2]; b[2 * p + 1][1] = t4[3];
            }
#pragma unroll
            for (int mf = 0; mf < 2; mf++)
#pragma unroll
                for (int nf = 0; nf < 4; nf++)
                    mma_f16(sacc[mf][nf], a[mf], b[nf]);
        }

        // exp, rowsum, P -> smem via stmatrix (bit-identical placement)
#pragma unroll
        for (int mf = 0; mf < 2; mf++) {
            uint32_t p01r[4], p23r[4];
#pragma unroll
            for (int nf = 0; nf < 4; nf++) {
                float e00 = fast_exp(sacc[mf][nf][0]);
                float e01 = fast_exp(sacc[mf][nf][1]);
                float e10 = fast_exp(sacc[mf][nf][2]);
                float e11 = fast_exp(sacc[mf][nf][3]);
                rsum[mf][0] += e00 + e01;
                rsum[mf][1] += e10 + e11;
                p01r[nf] = h2u(__floats2half2_rn(e00, e01));
                p23r[nf] = h2u(__floats2half2_rn(e10, e11));
            }
            stsm_x4(ps_u + poff + (uint32_t)(mf * 16 * AST) * 4, p01r);
            stsm_x4(ps_u + poff + (uint32_t)((mf * 16 + 8) * AST) * 4, p23r);
        }

        cp_wait0();            // V(kt) arrived
        __syncthreads();       // publish V + Ps; Ks fully consumed

        // issue K(kt+1) — overlaps the P·V phase below
        if (kt + 1 < S / 64) {
            const int nk0 = k0 + 64;
#pragma unroll
            for (int i = 0; i < 2; i++) {
                int idx = tid + i * 256;
                int row = idx >> 3, ch = idx & 7;
                cp16(ks_u + (uint32_t)(row * AST + ch * 4) * 4,
                     &g_kh[((size_t)bh * S + nk0 + row) * DK + ch * 8]);
            }
            cp_commit();
        }

        // ctx += P·V (4 fp16 k16 steps); ldmatrix frags
#pragma unroll
        for (int ks = 0; ks < 4; ks++) {
            const int kk = ks * 8;
            uint32_t a[2][4], b[4][2];
#pragma unroll
            for (int mf = 0; mf < 2; mf++)
                ldsm_x4(a[mf], ps_u + aoff + (uint32_t)(mf * 16 * AST + kk) * 4);
#pragma unroll
            for (int p = 0; p < 2; p++) {
                uint32_t t4[4];
                ldsm_x4(t4, vt_u + boff4 + (uint32_t)(p * 16 * AST + kk) * 4);
                b[2 * p + 0][0] = t4[0]; b[2 * p + 0][1] = t4[1];
                b[2 * p + 1][0] = t4[2]; b[2 * p + 1][1] = t4[3];
            }
#pragma unroll
            for (int mf = 0; mf < 2; mf++)
#pragma unroll
                for (int nf = 0; nf < 4; nf++)
                    mma_f16(cacc[mf][nf], a[mf], b[nf]);
        }

        // coalesced E writeback: Ps -> g_eh tile block (128 rows x 64 halfs)
        {
            __half* ebase = &g_eh[((size_t)bh * S + q0) * S + k0];
#pragma unroll
            for (int i = 0; i < 4; i++) {
                int idx = tid + i * 256;
                int row = idx >> 3, c4 = idx & 7;
                uint4 val = *(const uint4*)&Ps[row * AST + c4 * 4];
                *(uint4*)(ebase + (size_t)row * S + c4 * 8) = val;
            }
        }
        __syncthreads();       // Vt + Ps fully consumed

        // issue V(kt+1) — overlaps the next tile's QK phase
        if (kt + 1 < S / 64) {
            const int nk0 = k0 + 64;
#pragma unroll
            for (int i = 0; i < 2; i++) {
                int idx = tid + i * 256;
                int row = idx >> 3, ch = idx & 7;
                cp16(vt_u + (uint32_t)(row * AST + ch * 4) * 4,
                     &g_vt[((size_t)bh * DK + row) * S + nk0 + ch * 8]);
            }
            cp_commit();
        }
    }

    // rowsum: reduce across tq lanes (same g), publish per warp-column
#pragma unroll
    for (int mf = 0; mf < 2; mf++)
#pragma unroll
        for (int hh = 0; hh < 2; hh++) {
            float v = rsum[mf][hh];
            v += __shfl_xor_sync(0xffffffffu, v, 1);
            v += __shfl_xor_sync(0xffffffffu, v, 2);
            rsum[mf][hh] = v;
        }
    if (tq == 0) {
#pragma unroll
        for (int mf = 0; mf < 2; mf++)
#pragma unroll
            for (int hh = 0; hh < 2; hh++)
                rs[(wid & 1) * 128 + wm + mf * 16 + hh * 8 + g] = rsum[mf][hh];
    }
    __syncthreads();
    if (tid < 128) {
        float iv = 1.0f / (rs[tid] + rs[128 + tid]);
        g_rinv[(size_t)bh * S + q0 + tid] = iv;
        sinv[tid] = iv;
    }
    __syncthreads();

    // scaled ctx -> g_ctx (fp16: consumed only by fc's fp16 MMA)
    const int b_ = bh >> 4, h_ = bh & 15;
#pragma unroll
    for (int mf = 0; mf < 2; mf++) {
        const int r0 = wm + mf * 16 + g;
        const float iv0 = sinv[r0], iv1 = sinv[r0 + 8];
#pragma unroll
        for (int nf = 0; nf < 4; nf++) {
            const int c0 = wn + nf * 8 + tq * 2;
            *(__half2*)&g_ctx[((size_t)b_ * S + q0 + r0) * D + h_ * DK + c0] =
                __floats2half2_rn(cacc[mf][nf][0] * iv0, cacc[mf][nf][1] * iv0);
            *(__half2*)&g_ctx[((size_t)b_ * S + q0 + r0 + 8) * D + h_ * DK + c0] =
                __floats2half2_rn(cacc[mf][nf][2] * iv1, cacc[mf][nf][3] * iv1);
        }
    }
}

// ---------------------------------------------------------------------------
// K3: normalize: attn_out[row][*] = half2float(g_eh[row][*]) * rinv[row]
// ---------------------------------------------------------------------------
__global__ __launch_bounds__(256) void attn_scale_kernel(float* __restrict__ attn)
{
    size_t idx4 = (size_t)blockIdx.x * blockDim.x + threadIdx.x;  // 4-elem idx
    size_t row  = idx4 >> 9;                                      // 512 groups/row
    float inv = g_rinv[row];
    uint2 e = __ldcs((const uint2*)g_eh + idx4);
    __half2 h0, h1;
    __builtin_memcpy(&h0, &e.x, 4);
    __builtin_memcpy(&h1, &e.y, 4);
    float2 f0 = __half22float2(h0);
    float2 f1 = __half22float2(h1);
    float4 v = make_float4(f0.x * inv, f0.y * inv, f1.x * inv, f1.y * inv);
    __stcs((float4*)attn + idx4, v);
}

// ---------------------------------------------------------------------------
// K5: LayerNorm over last dim (1024). One block (256 thr) per row.
// ---------------------------------------------------------------------------
__global__ __launch_bounds__(256) void ln_kernel(
    const float* __restrict__ gamma, const float* __restrict__ beta,
    float* __restrict__ out)
{
    __shared__ float s1[8], s2[8];
    __shared__ float sm_mean, sm_rstd;
    const int row = blockIdx.x;
    const int t   = threadIdx.x;
    const float* x = g_x + (size_t)row * D;

    float4 v = *(const float4*)(x + t * 4);
    float sum = v.x + v.y + v.z + v.w;
    float sq  = v.x * v.x + v.y * v.y + v.z * v.z + v.w * v.w;
#pragma unroll
    for (int m = 16; m >= 1; m >>= 1) {
        sum += __shfl_xor_sync(0xffffffffu, sum, m);
        sq  += __shfl_xor_sync(0xffffffffu, sq, m);
    }
    const int warp = t >> 5, lane = t & 31;
    if (lane == 0) { s1[warp] = sum; s2[warp] = sq; }
    __syncthreads();
    if (t == 0) {
        float a = 0.f, c = 0.f;
#pragma unroll
        for (int w = 0; w < 8; w++) { a += s1[w]; c += s2[w]; }
        float mean = a * (1.0f / D);
        float var  = c * (1.0f / D) - mean * mean;
        sm_mean = mean;
        sm_rstd = rsqrtf(var + 1e-6f);
    }
    __syncthreads();
    const float mean = sm_mean, r = sm_rstd;
    float4 g4 = *(const float4*)(gamma + t * 4);
    float4 b4 = *(const float4*)(beta + t * 4);
    float4 o;
    o.x = (v.x - mean) * r * g4.x + b4.x;
    o.y = (v.y - mean) * r * g4.y + b4.y;
    o.z = (v.z - mean) * r * g4.z + b4.z;
    o.w = (v.w - mean) * r * g4.w + b4.w;
    *(float4*)(out + (size_t)row * D + t * 4) = o;
}

// ---------------------------------------------------------------------------
extern "C" void kernel_launch(void* const* d_in, const int* in_sizes, int n_in,
                              void* d_out, int out_size)
{
    const float* q     = (const float*)d_in[0];
    const float* k     = (const float*)d_in[1];
    const float* v     = (const float*)d_in[2];
    const float* Wq    = (const float*)d_in[3];
    const float* bq    = (const float*)d_in[4];
    const float* Wfc   = (const float*)d_in[5];
    const float* bfc   = (const float*)d_in[6];
    const float* gamma = (const float*)d_in[7];
    const float* beta  = (const float*)d_in[8];

    float* out_x    = (float*)d_out;
    float* out_attn = out_x + X_ELEMS;

    cudaFuncSetAttribute(gemm_f16_kernel,
                         cudaFuncAttributeMaxDynamicSharedMemorySize, GEMM_SMEM);
    cudaFuncSetAttribute(attn_mma_kernel,
                         cudaFuncAttributeMaxDynamicSharedMemorySize, ATTN_SMEM);

    __half *qcv_p, *kcv_p, *vcv_p, *wqt_p, *wfct_p, *ctx_p;
    float *x_p;
    cudaGetSymbolAddress((void**)&qcv_p,  g_qcv);
    cudaGetSymbolAddress((void**)&kcv_p,  g_kcv);
    cudaGetSymbolAddress((void**)&vcv_p,  g_vcv);
    cudaGetSymbolAddress((void**)&wqt_p,  g_wqt);
    cudaGetSymbolAddress((void**)&wfct_p, g_wfct);
    cudaGetSymbolAddress((void**)&ctx_p,  g_ctx);
    cudaGetSymbolAddress((void**)&x_p,    g_x);

    convert_kernel<<<dim3((unsigned)(X_ELEMS / 4 / 256), 3), 256>>>(q, k, v);
    transpose_kernel<<<dim3(32, 32, 2), dim3(32, 8)>>>(Wq, Wfc);
    gemm_f16_kernel<<<dim3(8, 64, 3), 256, GEMM_SMEM>>>(
        qcv_p, kcv_p, vcv_p, wqt_p, bq, nullptr, nullptr, 0);
    attn_mma_kernel<<<dim3(16, 64), 256, ATTN_SMEM>>>();
    attn_scale_kernel<<<(unsigned)(ATTN_ELEMS / 4 / 256), 256>>>(out_attn);
    gemm_f16_kernel<<<dim3(8, 64, 1), 256, GEMM_SMEM>>>(
        ctx_p, ctx_p, ctx_p, wfct_p, bfc, q, x_p, 1);
    ln_kernel<<<B * S, 256>>>(gamma, beta, out_x);
}